// round 13
// baseline (speedup 1.0000x reference)
#include <cuda_runtime.h>
#include <cuda_fp16.h>
#include <cstdint>

#define IN_F  4096
#define OUT_F 4096
#define NFAC  3

// ---------------- scratch (device globals; allocation forbidden) -----------
__device__ __align__(1024) float  g_Q[NFAC * 64 * 64 * 64];
__device__ int    g_pinv[NFAC * IN_F];
__device__ __align__(1024) __half g_hA[(size_t)OUT_F * IN_F];        // 32 MB
__device__ __align__(1024) __half g_hB[(size_t)OUT_F * IN_F];        // 32 MB
__device__ __align__(1024) __half g_xh[(size_t)8 * 2048 * IN_F];     // 128 MB

// ---------------- helpers ---------------------------------------------------
__device__ __forceinline__ uint32_t smem_u32(const void* p) {
    uint32_t a;
    asm("{ .reg .u64 t; cvta.to.shared.u64 t, %1; cvt.u32.u64 %0, t; }" : "=r"(a) : "l"(p));
    return a;
}
#define CP_ASYNC16(dst, src) \
    asm volatile("cp.async.cg.shared.global [%0], [%1], 16;" :: "r"(dst), "l"(src) : "memory")
#define CP_COMMIT()  asm volatile("cp.async.commit_group;" ::: "memory")
#define CP_WAIT1()   asm volatile("cp.async.wait_group 1;" ::: "memory")

#define LDSM4(r, addr) \
    asm volatile("ldmatrix.sync.aligned.m8n8.x4.shared.b16 {%0,%1,%2,%3}, [%4];" \
        : "=r"((r)[0]), "=r"((r)[1]), "=r"((r)[2]), "=r"((r)[3]) : "r"(addr))

#define MMA16816(c, a, b0v, b1v) \
    asm volatile("mma.sync.aligned.m16n8k16.row.col.f32.f16.f16.f32 " \
        "{%0,%1,%2,%3},{%4,%5,%6,%7},{%8,%9},{%0,%1,%2,%3};" \
        : "+f"((c)[0]), "+f"((c)[1]), "+f"((c)[2]), "+f"((c)[3]) \
        : "r"((a)[0]), "r"((a)[1]), "r"((a)[2]), "r"((a)[3]), "r"(b0v), "r"(b1v))

// ---- prep A: Cayley (0..191) | pinv (192) ----------------------------------
__global__ void prep_cayley_pinv(const float* __restrict__ R_all,
                                 const int* __restrict__ perm)
{
    const int tid = threadIdx.x;
    const int bid = blockIdx.x;

    if (bid == 192) {                // inverse permutation
        for (int idx = tid; idx < NFAC * IN_F; idx += 256) {
            int f = idx >> 12, j = idx & 4095;
            g_pinv[(f << 12) + perm[idx]] = j;
        }
        return;
    }

    // Cayley: Q = (I-S)(I+S)^-1 via GJ on [I-S | I+S]
    __shared__ float aug[64][129];
    const float* R = R_all + (size_t)bid * 4096;

    for (int idx = tid; idx < 4096; idx += 256) {
        int i = idx >> 6, j = idx & 63;
        float s = 0.5f * (R[i * 64 + j] - R[j * 64 + i]);
        float d = (i == j) ? 1.0f : 0.0f;
        aug[i][j]      = d - s;
        aug[i][64 + j] = d + s;
    }
    __syncthreads();

    const int r  = tid >> 2;
    const int c0 = tid & 3;
    for (int k = 0; k < 64; k++) {
        float inv = 1.0f / aug[k][k];
        __syncthreads();
        if (tid < 32) {
            #pragma unroll
            for (int i = 0; i < 4; i++) aug[k][tid + 32 * i] *= inv;
        }
        __syncthreads();
        float f = aug[r][k];
        __syncthreads();
        if (r != k) {
            #pragma unroll
            for (int i = 0; i < 32; i++) {
                int c = c0 + 4 * i;
                aug[r][c] -= f * aug[k][c];
            }
        }
        __syncthreads();
    }

    float* Qm = g_Q + (size_t)bid * 4096;
    for (int idx = tid; idx < 4096; idx += 256) {
        int a = idx >> 6, b = idx & 63;
        Qm[a * 64 + b] = aug[b][64 + a];
    }
}

// ---- prep B: x -> fp16 (runs on side stream, overlapped with rot chain) ---
__global__ void convert_x(const float4* __restrict__ xin, uint4* __restrict__ xout)
{
    int i = blockIdx.x * 256 + threadIdx.x;
    float4 a = xin[2 * i], b = xin[2 * i + 1];
    __half2 h0 = __floats2half2_rn(a.x, a.y);
    __half2 h1 = __floats2half2_rn(a.z, a.w);
    __half2 h2 = __floats2half2_rn(b.x, b.y);
    __half2 h3 = __floats2half2_rn(b.z, b.w);
    uint4 v;
    v.x = *(uint32_t*)&h0; v.y = *(uint32_t*)&h1;
    v.z = *(uint32_t*)&h2; v.w = *(uint32_t*)&h3;
    xout[i] = v;
}

// ------- one butterfly factor via HMMA: Wout = Wblock(128x64) * Q^T --------
__global__ __launch_bounds__(256) void rot_hmma(
    const float* __restrict__ WinF, const __half* __restrict__ WinH,
    __half* __restrict__ Wout, int factor, const float* __restrict__ s)
{
    __shared__ __align__(16) char sm[128 * 128 + 64 * 128];   // A tile + Q tile
    __shared__ int   cs[64];
    __shared__ float sv[128];
    const uint32_t sa = smem_u32(sm);
    const uint32_t sq = sa + 128 * 128;

    const int d    = blockIdx.x;      // 64-col block
    const int rg   = blockIdx.y;      // 128-row group
    const int tid  = threadIdx.x;
    const int row0 = rg * 128;

    if (tid < 64) cs[tid] = g_pinv[factor * IN_F + d * 64 + tid];
    if (s != nullptr && tid < 128) sv[tid] = s[row0 + tid];
    __syncthreads();

    // A tile: 128 rows x 64 halves (128B rows, XOR-swizzled 16B chunks)
    #pragma unroll
    for (int i = 0; i < 4; i++) {
        int q = tid + 256 * i;
        int r = q >> 3, c = q & 7;
        char* dst = sm + r * 128 + ((c ^ (r & 7)) << 4);
        int b0 = c * 8;
        if (WinF) {
            const float* src = &WinF[(size_t)(row0 + r) * IN_F + cs[b0]];
            float4 v0 = *(const float4*)src;
            float4 v1 = *(const float4*)(src + 4);
            __half2 h0 = __floats2half2_rn(v0.x, v0.y);
            __half2 h1 = __floats2half2_rn(v0.z, v0.w);
            __half2 h2 = __floats2half2_rn(v1.x, v1.y);
            __half2 h3 = __floats2half2_rn(v1.z, v1.w);
            uint4 u;
            u.x = *(uint32_t*)&h0; u.y = *(uint32_t*)&h1;
            u.z = *(uint32_t*)&h2; u.w = *(uint32_t*)&h3;
            *(uint4*)dst = u;
        } else {
            *(uint4*)dst = *(const uint4*)&WinH[(size_t)(row0 + r) * IN_F + cs[b0]];
        }
    }

    // Q tile: 64 rows (a) x 64 halves (b); convert fp32 -> fp16
    const float* Qm = g_Q + ((size_t)factor * 64 + d) * 4096;
    #pragma unroll
    for (int i = 0; i < 2; i++) {
        int q = tid + 256 * i;
        int r = q >> 3, c = q & 7;
        const float* src = &Qm[r * 64 + c * 8];
        float4 v0 = *(const float4*)src;
        float4 v1 = *(const float4*)(src + 4);
        __half2 h0 = __floats2half2_rn(v0.x, v0.y);
        __half2 h1 = __floats2half2_rn(v0.z, v0.w);
        __half2 h2 = __floats2half2_rn(v1.x, v1.y);
        __half2 h3 = __floats2half2_rn(v1.z, v1.w);
        uint4 u;
        u.x = *(uint32_t*)&h0; u.y = *(uint32_t*)&h1;
        u.z = *(uint32_t*)&h2; u.w = *(uint32_t*)&h3;
        *(uint4*)(sm + 128 * 128 + r * 128 + ((c ^ (r & 7)) << 4)) = u;
    }
    __syncthreads();

    // MMA: warp w computes rows [w*16, w*16+16) x all 64 cols
    const int wid = tid >> 5, lid = tid & 31;
    const int lrow = (lid & 7) + ((lid >> 3) & 1) * 8;
    const int lkhi = (lid >> 4) & 1;
    const int rowx = lrow & 7;
    const uint32_t a_base = sa + (wid * 16 + lrow) * 128;
    const uint32_t b_base = sq + lrow * 128;

    float acc[4][2][4];
    #pragma unroll
    for (int g = 0; g < 4; g++)
        #pragma unroll
        for (int j = 0; j < 2; j++)
            #pragma unroll
            for (int k = 0; k < 4; k++) acc[g][j][k] = 0.0f;

    #pragma unroll
    for (int kk = 0; kk < 4; kk++) {
        const uint32_t coff = ((((kk << 1) | lkhi) ^ rowx) << 4);
        uint32_t afr[4];
        LDSM4(afr, a_base + coff);
        uint32_t bfr[4][4];
        #pragma unroll
        for (int g = 0; g < 4; g++)
            LDSM4(bfr[g], b_base + g * 2048 + coff);
        #pragma unroll
        for (int g = 0; g < 4; g++) {
            MMA16816(acc[g][0], afr, bfr[g][0], bfr[g][2]);
            MMA16816(acc[g][1], afr, bfr[g][1], bfr[g][3]);
        }
    }

    // epilogue: scale (last pass), fp16 pack, scatter cols via cs
    const int mrow = lid >> 2;
    const int ncl  = (lid & 3) * 2;
    const int mloc0 = wid * 16 + mrow;
    float s0 = 1.0f, s1 = 1.0f;
    if (s != nullptr) { s0 = sv[mloc0]; s1 = sv[mloc0 + 8]; }
    #pragma unroll
    for (int g = 0; g < 4; g++)
        #pragma unroll
        for (int j = 0; j < 2; j++) {
            int n = g * 16 + j * 8 + ncl;
            int gcol = cs[n];                    // cs[n+1] == gcol+1 (run of 32)
            float* a4 = acc[g][j];
            __half2 h0 = __floats2half2_rn(a4[0] * s0, a4[1] * s0);
            __half2 h1 = __floats2half2_rn(a4[2] * s1, a4[3] * s1);
            *(__half2*)&Wout[(size_t)(row0 + mloc0) * IN_F + gcol]     = h0;
            *(__half2*)&Wout[(size_t)(row0 + mloc0 + 8) * IN_F + gcol] = h1;
        }
}

// ---------------- fp16 mma.sync GEMM: C[16384,4096] = A * B^T + bias -------
#define BKH 64
#define AST 16384
#define STG 32768
#define STAGES 3
#define SMEM_TOTAL (STAGES * STG)       // 98304

__global__ __launch_bounds__(128, 2) void gemm_hmma(
    const __half* __restrict__ A, const __half* __restrict__ B,
    const float* __restrict__ bias, float* __restrict__ C)
{
    extern __shared__ char smem[];
    const uint32_t sb = smem_u32(smem);
    const int tid = threadIdx.x;
    const int wid = tid >> 5, lid = tid & 31;
    const int wm  = wid >> 1, wn = wid & 1;
    const int m0  = blockIdx.y * 128;
    const int n0  = blockIdx.x * 128;

    float acc[4][4][2][4];
    #pragma unroll
    for (int mi = 0; mi < 4; mi++)
        #pragma unroll
        for (int g = 0; g < 4; g++)
            #pragma unroll
            for (int j = 0; j < 2; j++)
                #pragma unroll
                for (int k = 0; k < 4; k++) acc[mi][g][j][k] = 0.0f;

    auto load_stage = [&](int st, int kt) {
        const uint32_t ab = sb + st * STG;
        const uint32_t bb = ab + AST;
        const __half* Ag = A + (size_t)m0 * IN_F + kt * BKH;
        const __half* Bg = B + (size_t)n0 * IN_F + kt * BKH;
        #pragma unroll
        for (int i = 0; i < 8; i++) {
            int q = tid + 128 * i;
            int r = q >> 3, c = q & 7;
            CP_ASYNC16(ab + r * 128 + ((c ^ (r & 7)) << 4), Ag + (size_t)r * IN_F + c * 8);
        }
        #pragma unroll
        for (int i = 0; i < 8; i++) {
            int q = tid + 128 * i;
            int r = q >> 3, c = q & 7;
            CP_ASYNC16(bb + r * 128 + ((c ^ (r & 7)) << 4), Bg + (size_t)r * IN_F + c * 8);
        }
    };

    load_stage(0, 0); CP_COMMIT();
    load_stage(1, 1); CP_COMMIT();

    const int lrow = (lid & 7) + ((lid >> 3) & 1) * 8;
    const int lkhi = (lid >> 4) & 1;
    const int rowx = lrow & 7;

    const int NK = IN_F / BKH;    // 64
    for (int kt = 0; kt < NK; kt++) {
        CP_WAIT1();
        __syncthreads();
        const uint32_t as = sb + (kt % STAGES) * STG;
        const uint32_t bs = as + AST;
        const uint32_t a_base = as + (wm * 64 + lrow) * 128;
        const uint32_t b_base = bs + (wn * 64 + lrow) * 128;

        #pragma unroll
        for (int kk = 0; kk < 4; kk++) {
            const uint32_t coff = ((((kk << 1) | lkhi) ^ rowx) << 4);
            uint32_t afr[4][4];
            #pragma unroll
            for (int mi = 0; mi < 4; mi++)
                LDSM4(afr[mi], a_base + mi * 2048 + coff);
            uint32_t bfr[4][4];
            #pragma unroll
            for (int g = 0; g < 4; g++)
                LDSM4(bfr[g], b_base + g * 2048 + coff);
            #pragma unroll
            for (int mi = 0; mi < 4; mi++)
                #pragma unroll
                for (int g = 0; g < 4; g++) {
                    MMA16816(acc[mi][g][0], afr[mi], bfr[g][0], bfr[g][2]);
                    MMA16816(acc[mi][g][1], afr[mi], bfr[g][1], bfr[g][3]);
                }
        }

        if (kt + 2 < NK) load_stage((kt + 2) % STAGES, kt + 2);
        CP_COMMIT();
    }

    // epilogue: fused bias, float2 stores
    const int mrow = lid >> 2;
    const int ncl  = (lid & 3) * 2;
    #pragma unroll
    for (int g = 0; g < 4; g++)
        #pragma unroll
        for (int j = 0; j < 2; j++) {
            int n = n0 + wn * 64 + g * 16 + j * 8 + ncl;
            float2 bv = *(const float2*)&bias[n];
            #pragma unroll
            for (int mi = 0; mi < 4; mi++) {
                int m = m0 + wm * 64 + mi * 16 + mrow;
                float* a4 = acc[mi][g][j];
                float2 v0 = { a4[0] + bv.x, a4[1] + bv.y };
                float2 v1 = { a4[2] + bv.x, a4[3] + bv.y };
                *(float2*)&C[(size_t)m * OUT_F + n]       = v0;
                *(float2*)&C[(size_t)(m + 8) * OUT_F + n] = v1;
            }
        }
}

// ---------------- launch ----------------
extern "C" void kernel_launch(void* const* d_in, const int* in_sizes, int n_in,
                              void* d_out, int out_size)
{
    const float* x      = (const float*)d_in[0];
    const float* weight = (const float*)d_in[1];
    const float* bias   = (const float*)d_in[2];
    const float* boft_R = (const float*)d_in[3];
    const float* boft_s = (const float*)d_in[4];
    const int*   perm   = (const int*)d_in[5];
    float* out = (float*)d_out;

    __half *hA, *hB, *xh;
    cudaGetSymbolAddress((void**)&hA, g_hA);
    cudaGetSymbolAddress((void**)&hB, g_hB);
    cudaGetSymbolAddress((void**)&xh, g_xh);

    // one-time side stream + events (handle reuse; no device memory)
    static cudaStream_t s2 = nullptr;
    static cudaEvent_t evFork = nullptr, evJoin = nullptr;
    if (!s2) {
        cudaStreamCreateWithFlags(&s2, cudaStreamNonBlocking);
        cudaEventCreateWithFlags(&evFork, cudaEventDisableTiming);
        cudaEventCreateWithFlags(&evJoin, cudaEventDisableTiming);
    }

    // fork: convert_x runs concurrently with cayley + rot chain
    cudaEventRecord(evFork, 0);
    cudaStreamWaitEvent(s2, evFork, 0);
    convert_x<<<32768, 256, 0, s2>>>((const float4*)x, (uint4*)xh);
    cudaEventRecord(evJoin, s2);

    prep_cayley_pinv<<<193, 256>>>(boft_R, perm);
    rot_hmma<<<dim3(64, 32), 256>>>(weight,  nullptr, hA, 0, nullptr);
    rot_hmma<<<dim3(64, 32), 256>>>(nullptr, hA,      hB, 1, nullptr);
    rot_hmma<<<dim3(64, 32), 256>>>(nullptr, hB,      hA, 2, boft_s);

    // join: gemm needs both xh (s2) and hA (stream 0)
    cudaStreamWaitEvent(0, evJoin, 0);
    cudaFuncSetAttribute(gemm_hmma, cudaFuncAttributeMaxDynamicSharedMemorySize, SMEM_TOTAL);
    gemm_hmma<<<dim3(OUT_F / 128, 16384 / 128), 128, SMEM_TOTAL>>>(xh, hA, bias, out);
}

// round 14
// speedup vs baseline: 1.1844x; 1.1844x over previous
#include <cuda_runtime.h>
#include <cuda_fp16.h>
#include <cstdint>

#define IN_F  4096
#define OUT_F 4096
#define NFAC  3

// ---------------- scratch (device globals; allocation forbidden) -----------
__device__ __align__(1024) float  g_Q[NFAC * 64 * 64 * 64];
__device__ int    g_pinv[NFAC * IN_F];
__device__ __align__(1024) __half g_hA[(size_t)OUT_F * IN_F];        // 32 MB
__device__ __align__(1024) __half g_hB[(size_t)OUT_F * IN_F];        // 32 MB
__device__ __align__(1024) __half g_xh[(size_t)8 * 2048 * IN_F];     // 128 MB

// ---------------- helpers ---------------------------------------------------
__device__ __forceinline__ uint32_t smem_u32(const void* p) {
    uint32_t a;
    asm("{ .reg .u64 t; cvta.to.shared.u64 t, %1; cvt.u32.u64 %0, t; }" : "=r"(a) : "l"(p));
    return a;
}
#define CP_ASYNC16(dst, src) \
    asm volatile("cp.async.cg.shared.global [%0], [%1], 16;" :: "r"(dst), "l"(src) : "memory")
#define CP_COMMIT()  asm volatile("cp.async.commit_group;" ::: "memory")
#define CP_WAIT1()   asm volatile("cp.async.wait_group 1;" ::: "memory")

#define LDSM4(r, addr) \
    asm volatile("ldmatrix.sync.aligned.m8n8.x4.shared.b16 {%0,%1,%2,%3}, [%4];" \
        : "=r"((r)[0]), "=r"((r)[1]), "=r"((r)[2]), "=r"((r)[3]) : "r"(addr))

#define MMA16816(c, a, b0v, b1v) \
    asm volatile("mma.sync.aligned.m16n8k16.row.col.f32.f16.f16.f32 " \
        "{%0,%1,%2,%3},{%4,%5,%6,%7},{%8,%9},{%0,%1,%2,%3};" \
        : "+f"((c)[0]), "+f"((c)[1]), "+f"((c)[2]), "+f"((c)[3]) \
        : "r"((a)[0]), "r"((a)[1]), "r"((a)[2]), "r"((a)[3]), "r"(b0v), "r"(b1v))

// ---- prep: Cayley (0..191) | pinv (192) ------------------------------------
__global__ void prep_cayley_pinv(const float* __restrict__ R_all,
                                 const int* __restrict__ perm)
{
    const int tid = threadIdx.x;
    const int bid = blockIdx.x;

    if (bid == 192) {                // inverse permutation
        for (int idx = tid; idx < NFAC * IN_F; idx += 256) {
            int f = idx >> 12, j = idx & 4095;
            g_pinv[(f << 12) + perm[idx]] = j;
        }
        return;
    }

    // Cayley: Q = (I-S)(I+S)^-1 via GJ on [I-S | I+S]
    __shared__ float aug[64][129];
    const float* R = R_all + (size_t)bid * 4096;

    for (int idx = tid; idx < 4096; idx += 256) {
        int i = idx >> 6, j = idx & 63;
        float s = 0.5f * (R[i * 64 + j] - R[j * 64 + i]);
        float d = (i == j) ? 1.0f : 0.0f;
        aug[i][j]      = d - s;
        aug[i][64 + j] = d + s;
    }
    __syncthreads();

    const int r  = tid >> 2;
    const int c0 = tid & 3;
    for (int k = 0; k < 64; k++) {
        float inv = 1.0f / aug[k][k];
        __syncthreads();
        if (tid < 32) {
            #pragma unroll
            for (int i = 0; i < 4; i++) aug[k][tid + 32 * i] *= inv;
        }
        __syncthreads();
        float f = aug[r][k];
        __syncthreads();
        if (r != k) {
            #pragma unroll
            for (int i = 0; i < 32; i++) {
                int c = c0 + 4 * i;
                aug[r][c] -= f * aug[k][c];
            }
        }
        __syncthreads();
    }

    float* Qm = g_Q + (size_t)bid * 4096;
    for (int idx = tid; idx < 4096; idx += 256) {
        int a = idx >> 6, b = idx & 63;
        Qm[a * 64 + b] = aug[b][64 + a];
    }
}

// ------- one butterfly factor via HMMA, with piggybacked x->fp16 blocks ----
// Blocks [0, 2048): rot pass (d = bid & 63, rg = bid >> 6).
// Blocks [2048, 2048 + nconv): convert x chunk (index offset convBase).
#define ROT_BLOCKS 2048

__global__ __launch_bounds__(256) void rot_hmma_conv(
    const float* __restrict__ WinF, const __half* __restrict__ WinH,
    __half* __restrict__ Wout, int factor, const float* __restrict__ s,
    const float4* __restrict__ xin, uint4* __restrict__ xout, int convBase)
{
    const int bid = blockIdx.x;
    const int tid = threadIdx.x;

    if (bid >= ROT_BLOCKS) {            // ---- convert_x part ----
        int i = (convBase + (bid - ROT_BLOCKS)) * 256 + tid;
        float4 a = xin[2 * i], b = xin[2 * i + 1];
        __half2 h0 = __floats2half2_rn(a.x, a.y);
        __half2 h1 = __floats2half2_rn(a.z, a.w);
        __half2 h2 = __floats2half2_rn(b.x, b.y);
        __half2 h3 = __floats2half2_rn(b.z, b.w);
        uint4 v;
        v.x = *(uint32_t*)&h0; v.y = *(uint32_t*)&h1;
        v.z = *(uint32_t*)&h2; v.w = *(uint32_t*)&h3;
        xout[i] = v;
        return;
    }

    // ---- rot part (identical math to R12's rot_hmma) ----
    __shared__ __align__(16) char sm[128 * 128 + 64 * 128];   // A tile + Q tile
    __shared__ int   cs[64];
    __shared__ float sv[128];
    const uint32_t sa = smem_u32(sm);
    const uint32_t sq = sa + 128 * 128;

    const int d    = bid & 63;        // 64-col block
    const int rg   = bid >> 6;        // 128-row group
    const int row0 = rg * 128;

    if (tid < 64) cs[tid] = g_pinv[factor * IN_F + d * 64 + tid];
    if (s != nullptr && tid < 128) sv[tid] = s[row0 + tid];
    __syncthreads();

    // A tile: 128 rows x 64 halves (128B rows, XOR-swizzled 16B chunks)
    #pragma unroll
    for (int i = 0; i < 4; i++) {
        int q = tid + 256 * i;
        int r = q >> 3, c = q & 7;
        char* dst = sm + r * 128 + ((c ^ (r & 7)) << 4);
        int b0 = c * 8;
        if (WinF) {
            const float* src = &WinF[(size_t)(row0 + r) * IN_F + cs[b0]];
            float4 v0 = *(const float4*)src;
            float4 v1 = *(const float4*)(src + 4);
            __half2 h0 = __floats2half2_rn(v0.x, v0.y);
            __half2 h1 = __floats2half2_rn(v0.z, v0.w);
            __half2 h2 = __floats2half2_rn(v1.x, v1.y);
            __half2 h3 = __floats2half2_rn(v1.z, v1.w);
            uint4 u;
            u.x = *(uint32_t*)&h0; u.y = *(uint32_t*)&h1;
            u.z = *(uint32_t*)&h2; u.w = *(uint32_t*)&h3;
            *(uint4*)dst = u;
        } else {
            *(uint4*)dst = *(const uint4*)&WinH[(size_t)(row0 + r) * IN_F + cs[b0]];
        }
    }

    // Q tile: 64 rows (a) x 64 halves (b); convert fp32 -> fp16
    const float* Qm = g_Q + ((size_t)factor * 64 + d) * 4096;
    #pragma unroll
    for (int i = 0; i < 2; i++) {
        int q = tid + 256 * i;
        int r = q >> 3, c = q & 7;
        const float* src = &Qm[r * 64 + c * 8];
        float4 v0 = *(const float4*)src;
        float4 v1 = *(const float4*)(src + 4);
        __half2 h0 = __floats2half2_rn(v0.x, v0.y);
        __half2 h1 = __floats2half2_rn(v0.z, v0.w);
        __half2 h2 = __floats2half2_rn(v1.x, v1.y);
        __half2 h3 = __floats2half2_rn(v1.z, v1.w);
        uint4 u;
        u.x = *(uint32_t*)&h0; u.y = *(uint32_t*)&h1;
        u.z = *(uint32_t*)&h2; u.w = *(uint32_t*)&h3;
        *(uint4*)(sm + 128 * 128 + r * 128 + ((c ^ (r & 7)) << 4)) = u;
    }
    __syncthreads();

    // MMA: warp w computes rows [w*16, w*16+16) x all 64 cols
    const int wid = tid >> 5, lid = tid & 31;
    const int lrow = (lid & 7) + ((lid >> 3) & 1) * 8;
    const int lkhi = (lid >> 4) & 1;
    const int rowx = lrow & 7;
    const uint32_t a_base = sa + (wid * 16 + lrow) * 128;
    const uint32_t b_base = sq + lrow * 128;

    float acc[4][2][4];
    #pragma unroll
    for (int g = 0; g < 4; g++)
        #pragma unroll
        for (int j = 0; j < 2; j++)
            #pragma unroll
            for (int k = 0; k < 4; k++) acc[g][j][k] = 0.0f;

    #pragma unroll
    for (int kk = 0; kk < 4; kk++) {
        const uint32_t coff = ((((kk << 1) | lkhi) ^ rowx) << 4);
        uint32_t afr[4];
        LDSM4(afr, a_base + coff);
        uint32_t bfr[4][4];
        #pragma unroll
        for (int g = 0; g < 4; g++)
            LDSM4(bfr[g], b_base + g * 2048 + coff);
        #pragma unroll
        for (int g = 0; g < 4; g++) {
            MMA16816(acc[g][0], afr, bfr[g][0], bfr[g][2]);
            MMA16816(acc[g][1], afr, bfr[g][1], bfr[g][3]);
        }
    }

    // epilogue: scale (last pass), fp16 pack, scatter cols via cs
    const int mrow = lid >> 2;
    const int ncl  = (lid & 3) * 2;
    const int mloc0 = wid * 16 + mrow;
    float s0 = 1.0f, s1 = 1.0f;
    if (s != nullptr) { s0 = sv[mloc0]; s1 = sv[mloc0 + 8]; }
    #pragma unroll
    for (int g = 0; g < 4; g++)
        #pragma unroll
        for (int j = 0; j < 2; j++) {
            int n = g * 16 + j * 8 + ncl;
            int gcol = cs[n];                    // cs[n+1] == gcol+1 (run of 32)
            float* a4 = acc[g][j];
            __half2 h0 = __floats2half2_rn(a4[0] * s0, a4[1] * s0);
            __half2 h1 = __floats2half2_rn(a4[2] * s1, a4[3] * s1);
            *(__half2*)&Wout[(size_t)(row0 + mloc0) * IN_F + gcol]     = h0;
            *(__half2*)&Wout[(size_t)(row0 + mloc0 + 8) * IN_F + gcol] = h1;
        }
}

// ---------------- fp16 mma.sync GEMM: C[16384,4096] = A * B^T + bias -------
#define BKH 64
#define AST 16384
#define STG 32768
#define STAGES 3
#define SMEM_TOTAL (STAGES * STG)       // 98304

__global__ __launch_bounds__(128, 2) void gemm_hmma(
    const __half* __restrict__ A, const __half* __restrict__ B,
    const float* __restrict__ bias, float* __restrict__ C)
{
    extern __shared__ char smem[];
    const uint32_t sb = smem_u32(smem);
    const int tid = threadIdx.x;
    const int wid = tid >> 5, lid = tid & 31;
    const int wm  = wid >> 1, wn = wid & 1;
    const int m0  = blockIdx.y * 128;
    const int n0  = blockIdx.x * 128;

    float acc[4][4][2][4];
    #pragma unroll
    for (int mi = 0; mi < 4; mi++)
        #pragma unroll
        for (int g = 0; g < 4; g++)
            #pragma unroll
            for (int j = 0; j < 2; j++)
                #pragma unroll
                for (int k = 0; k < 4; k++) acc[mi][g][j][k] = 0.0f;

    auto load_stage = [&](int st, int kt) {
        const uint32_t ab = sb + st * STG;
        const uint32_t bb = ab + AST;
        const __half* Ag = A + (size_t)m0 * IN_F + kt * BKH;
        const __half* Bg = B + (size_t)n0 * IN_F + kt * BKH;
        #pragma unroll
        for (int i = 0; i < 8; i++) {
            int q = tid + 128 * i;
            int r = q >> 3, c = q & 7;
            CP_ASYNC16(ab + r * 128 + ((c ^ (r & 7)) << 4), Ag + (size_t)r * IN_F + c * 8);
        }
        #pragma unroll
        for (int i = 0; i < 8; i++) {
            int q = tid + 128 * i;
            int r = q >> 3, c = q & 7;
            CP_ASYNC16(bb + r * 128 + ((c ^ (r & 7)) << 4), Bg + (size_t)r * IN_F + c * 8);
        }
    };

    load_stage(0, 0); CP_COMMIT();
    load_stage(1, 1); CP_COMMIT();

    const int lrow = (lid & 7) + ((lid >> 3) & 1) * 8;
    const int lkhi = (lid >> 4) & 1;
    const int rowx = lrow & 7;

    const int NK = IN_F / BKH;    // 64
    for (int kt = 0; kt < NK; kt++) {
        CP_WAIT1();
        __syncthreads();
        const uint32_t as = sb + (kt % STAGES) * STG;
        const uint32_t bs = as + AST;
        const uint32_t a_base = as + (wm * 64 + lrow) * 128;
        const uint32_t b_base = bs + (wn * 64 + lrow) * 128;

        #pragma unroll
        for (int kk = 0; kk < 4; kk++) {
            const uint32_t coff = ((((kk << 1) | lkhi) ^ rowx) << 4);
            uint32_t afr[4][4];
            #pragma unroll
            for (int mi = 0; mi < 4; mi++)
                LDSM4(afr[mi], a_base + mi * 2048 + coff);
            uint32_t bfr[4][4];
            #pragma unroll
            for (int g = 0; g < 4; g++)
                LDSM4(bfr[g], b_base + g * 2048 + coff);
            #pragma unroll
            for (int mi = 0; mi < 4; mi++)
                #pragma unroll
                for (int g = 0; g < 4; g++) {
                    MMA16816(acc[mi][g][0], afr[mi], bfr[g][0], bfr[g][2]);
                    MMA16816(acc[mi][g][1], afr[mi], bfr[g][1], bfr[g][3]);
                }
        }

        if (kt + 2 < NK) load_stage((kt + 2) % STAGES, kt + 2);
        CP_COMMIT();
    }

    // epilogue: fused bias, float2 stores
    const int mrow = lid >> 2;
    const int ncl  = (lid & 3) * 2;
    #pragma unroll
    for (int g = 0; g < 4; g++)
        #pragma unroll
        for (int j = 0; j < 2; j++) {
            int n = n0 + wn * 64 + g * 16 + j * 8 + ncl;
            float2 bv = *(const float2*)&bias[n];
            #pragma unroll
            for (int mi = 0; mi < 4; mi++) {
                int m = m0 + wm * 64 + mi * 16 + mrow;
                float* a4 = acc[mi][g][j];
                float2 v0 = { a4[0] + bv.x, a4[1] + bv.y };
                float2 v1 = { a4[2] + bv.x, a4[3] + bv.y };
                *(float2*)&C[(size_t)m * OUT_F + n]       = v0;
                *(float2*)&C[(size_t)(m + 8) * OUT_F + n] = v1;
            }
        }
}

// ---------------- launch ----------------
extern "C" void kernel_launch(void* const* d_in, const int* in_sizes, int n_in,
                              void* d_out, int out_size)
{
    const float* x      = (const float*)d_in[0];
    const float* weight = (const float*)d_in[1];
    const float* bias   = (const float*)d_in[2];
    const float* boft_R = (const float*)d_in[3];
    const float* boft_s = (const float*)d_in[4];
    const int*   perm   = (const int*)d_in[5];
    float* out = (float*)d_out;

    __half *hA, *hB, *xh;
    cudaGetSymbolAddress((void**)&hA, g_hA);
    cudaGetSymbolAddress((void**)&hB, g_hB);
    cudaGetSymbolAddress((void**)&xh, g_xh);

    // 32768 convert blocks total, split across rot pass 0 and pass 1
    const int CONV_HALF = 16384;

    prep_cayley_pinv<<<193, 256>>>(boft_R, perm);
    rot_hmma_conv<<<ROT_BLOCKS + CONV_HALF, 256>>>(
        weight,  nullptr, hA, 0, nullptr, (const float4*)x, (uint4*)xh, 0);
    rot_hmma_conv<<<ROT_BLOCKS + CONV_HALF, 256>>>(
        nullptr, hA,      hB, 1, nullptr, (const float4*)x, (uint4*)xh, CONV_HALF);
    rot_hmma_conv<<<ROT_BLOCKS, 256>>>(
        nullptr, hB,      hA, 2, boft_s,  (const float4*)x, (uint4*)xh, 0);

    cudaFuncSetAttribute(gemm_hmma, cudaFuncAttributeMaxDynamicSharedMemorySize, SMEM_TOTAL);
    gemm_hmma<<<dim3(OUT_F / 128, 16384 / 128), 128, SMEM_TOTAL>>>(xh, hA, bias, out);
}

// round 15
// speedup vs baseline: 1.2255x; 1.0346x over previous
#include <cuda_runtime.h>
#include <cuda_fp16.h>
#include <cstdint>

#define IN_F  4096
#define OUT_F 4096
#define NFAC  3

// ---------------- scratch (device globals; allocation forbidden) -----------
__device__ __align__(1024) float  g_Q[NFAC * 64 * 64 * 64];
__device__ int    g_pinv[NFAC * IN_F];
__device__ __align__(1024) __half g_hA[(size_t)OUT_F * IN_F];        // 32 MB
__device__ __align__(1024) __half g_hB[(size_t)OUT_F * IN_F];        // 32 MB
__device__ __align__(1024) __half g_xh[(size_t)8 * 2048 * IN_F];     // 128 MB

// ---------------- helpers ---------------------------------------------------
__device__ __forceinline__ uint32_t smem_u32(const void* p) {
    uint32_t a;
    asm("{ .reg .u64 t; cvta.to.shared.u64 t, %1; cvt.u32.u64 %0, t; }" : "=r"(a) : "l"(p));
    return a;
}
#define CP_ASYNC16(dst, src) \
    asm volatile("cp.async.cg.shared.global [%0], [%1], 16;" :: "r"(dst), "l"(src) : "memory")
#define CP_COMMIT()  asm volatile("cp.async.commit_group;" ::: "memory")
#define CP_WAIT1()   asm volatile("cp.async.wait_group 1;" ::: "memory")

#define LDSM4(r, addr) \
    asm volatile("ldmatrix.sync.aligned.m8n8.x4.shared.b16 {%0,%1,%2,%3}, [%4];" \
        : "=r"((r)[0]), "=r"((r)[1]), "=r"((r)[2]), "=r"((r)[3]) : "r"(addr))

#define MMA16816(c, a, b0v, b1v) \
    asm volatile("mma.sync.aligned.m16n8k16.row.col.f32.f16.f16.f32 " \
        "{%0,%1,%2,%3},{%4,%5,%6,%7},{%8,%9},{%0,%1,%2,%3};" \
        : "+f"((c)[0]), "+f"((c)[1]), "+f"((c)[2]), "+f"((c)[3]) \
        : "r"((a)[0]), "r"((a)[1]), "r"((a)[2]), "r"((a)[3]), "r"(b0v), "r"(b1v))

__device__ __forceinline__ uint4 cvt8f(const float* src) {
    float4 v0 = *(const float4*)src;
    float4 v1 = *(const float4*)(src + 4);
    __half2 h0 = __floats2half2_rn(v0.x, v0.y);
    __half2 h1 = __floats2half2_rn(v0.z, v0.w);
    __half2 h2 = __floats2half2_rn(v1.x, v1.y);
    __half2 h3 = __floats2half2_rn(v1.z, v1.w);
    uint4 u;
    u.x = *(uint32_t*)&h0; u.y = *(uint32_t*)&h1;
    u.z = *(uint32_t*)&h2; u.w = *(uint32_t*)&h3;
    return u;
}

// ---- fused prep: Cayley (0..191) | pinv (192) | x->fp16 (193..) -----------
__global__ void prep_kernel(const float* __restrict__ R_all,
                            const int* __restrict__ perm,
                            const float4* __restrict__ xin,
                            uint4* __restrict__ xout)
{
    const int tid = threadIdx.x;
    const int bid = blockIdx.x;

    if (bid > 192) {                 // x conversion
        int i = (bid - 193) * 256 + tid;
        float4 a = xin[2 * i], b = xin[2 * i + 1];
        __half2 h0 = __floats2half2_rn(a.x, a.y);
        __half2 h1 = __floats2half2_rn(a.z, a.w);
        __half2 h2 = __floats2half2_rn(b.x, b.y);
        __half2 h3 = __floats2half2_rn(b.z, b.w);
        uint4 v;
        v.x = *(uint32_t*)&h0; v.y = *(uint32_t*)&h1;
        v.z = *(uint32_t*)&h2; v.w = *(uint32_t*)&h3;
        xout[i] = v;
        return;
    }
    if (bid == 192) {                // inverse permutation
        for (int idx = tid; idx < NFAC * IN_F; idx += 256) {
            int f = idx >> 12, j = idx & 4095;
            g_pinv[(f << 12) + perm[idx]] = j;
        }
        return;
    }

    // Cayley: Q = (I-S)(I+S)^-1 via GJ on [I-S | I+S]
    __shared__ float aug[64][129];
    const float* R = R_all + (size_t)bid * 4096;

    for (int idx = tid; idx < 4096; idx += 256) {
        int i = idx >> 6, j = idx & 63;
        float s = 0.5f * (R[i * 64 + j] - R[j * 64 + i]);
        float d = (i == j) ? 1.0f : 0.0f;
        aug[i][j]      = d - s;
        aug[i][64 + j] = d + s;
    }
    __syncthreads();

    const int r  = tid >> 2;
    const int c0 = tid & 3;
    for (int k = 0; k < 64; k++) {
        float inv = 1.0f / aug[k][k];
        __syncthreads();
        if (tid < 32) {
            #pragma unroll
            for (int i = 0; i < 4; i++) aug[k][tid + 32 * i] *= inv;
        }
        __syncthreads();
        float f = aug[r][k];
        __syncthreads();
        if (r != k) {
            #pragma unroll
            for (int i = 0; i < 32; i++) {
                int c = c0 + 4 * i;
                aug[r][c] -= f * aug[k][c];
            }
        }
        __syncthreads();
    }

    float* Qm = g_Q + (size_t)bid * 4096;
    for (int idx = tid; idx < 4096; idx += 256) {
        int a = idx >> 6, b = idx & 63;
        Qm[a * 64 + b] = aug[b][64 + a];
    }
}

// ------- FUSED factors 0+1 via HMMA on 128x128 tiles ------------------------
// f0 perm lives in 64-col groups, f1 in 128-col groups -> 128-col tile closed.
// Each warp owns 16 rows end-to-end: phase-1 result scattered to smem in
// f1-coords via composite table c01 (runs-of-32 => half2-contiguous), then
// phase-2 MMA and gmem scatter via cs1. No block sync after the load sync.
#define R01_SMEM (32768 + 32768 + 4 * 128 * 4)   // T(2x16K) + Q(4x8K) + tables

__global__ __launch_bounds__(256) void rot01_hmma(
    const float* __restrict__ W, __half* __restrict__ Wout)
{
    extern __shared__ char sm01[];
    const uint32_t sT = smem_u32(sm01);          // T0; T1 at +16384
    const uint32_t sQ = sT + 32768;              // Q[f*2+sb] at +blk*8192
    int* cs0  = (int*)(sm01 + 65536);
    int* cs1  = cs0 + 128;
    int* c01  = cs1 + 128;
    int* inv1 = c01 + 128;

    const int g    = blockIdx.x;   // 128-col group
    const int rg   = blockIdx.y;   // 128-row group
    const int tid  = threadIdx.x;
    const int col0 = g * 128;
    const int row0 = rg * 128;

    if (tid < 128) {
        cs0[tid] = g_pinv[col0 + tid];
        cs1[tid] = g_pinv[4096 + col0 + tid];
    }
    __syncthreads();
    if (tid < 128) inv1[cs1[tid] - col0] = tid;
    __syncthreads();
    if (tid < 128) c01[tid] = inv1[cs0[tid] - col0];

    // T: gather W cols in f0-coords, fp32 -> fp16, 2 swizzled 128B-row tiles
    #pragma unroll
    for (int i = 0; i < 8; i++) {
        int q = tid + 256 * i;                 // 2048 16B chunks
        int sub = q >> 10, rr = (q >> 3) & 127, c = q & 7;
        int t = sub * 64 + c * 8;              // 8-aligned inside a 32-run
        uint4 u = cvt8f(&W[(size_t)(row0 + rr) * IN_F + cs0[t]]);
        *(uint4*)(sm01 + sub * 16384 + rr * 128 + ((c ^ (rr & 7)) << 4)) = u;
    }

    // Q: 4 blocks (f=0/1 x sb=0/1), fp32 -> fp16 swizzled
    #pragma unroll
    for (int i = 0; i < 8; i++) {
        int q = tid + 256 * i;                 // 2048 16B chunks
        int blk = q >> 9, r = (q >> 3) & 63, c = q & 7;
        int f = blk >> 1, sb = blk & 1;
        uint4 u = cvt8f(&g_Q[((size_t)f * 64 + 2 * g + sb) * 4096 + r * 64 + c * 8]);
        *(uint4*)(sm01 + 32768 + blk * 8192 + r * 128 + ((c ^ (r & 7)) << 4)) = u;
    }
    __syncthreads();

    const int wid = tid >> 5, lid = tid & 31;
    const int lrow = (lid & 7) + ((lid >> 3) & 1) * 8;
    const int lkhi = (lid >> 4) & 1;
    const int rowx = lrow & 7;
    const int arow = wid * 16 + lrow;
    const int mrow = lid >> 2;
    const int ncl  = (lid & 3) * 2;
    const int ml0  = wid * 16 + mrow;          // local row (and ml0+8)

    float acc[2][4][2][4];

    // ---------------- phase 1: factor 0 ----------------
    #pragma unroll
    for (int sb = 0; sb < 2; sb++) {
        #pragma unroll
        for (int gg = 0; gg < 4; gg++)
            #pragma unroll
            for (int j = 0; j < 2; j++)
                #pragma unroll
                for (int k = 0; k < 4; k++) acc[sb][gg][j][k] = 0.0f;
        const uint32_t a_base = sT + sb * 16384 + arow * 128;
        const uint32_t b_base = sQ + sb * 8192 + lrow * 128;   // f=0
        #pragma unroll
        for (int kk = 0; kk < 4; kk++) {
            const uint32_t coff = ((((kk << 1) | lkhi) ^ rowx) << 4);
            uint32_t afr[4];
            LDSM4(afr, a_base + coff);
            uint32_t bfr[4][4];
            #pragma unroll
            for (int gg = 0; gg < 4; gg++)
                LDSM4(bfr[gg], b_base + gg * 2048 + coff);
            #pragma unroll
            for (int gg = 0; gg < 4; gg++) {
                MMA16816(acc[sb][gg][0], afr, bfr[gg][0], bfr[gg][2]);
                MMA16816(acc[sb][gg][1], afr, bfr[gg][1], bfr[gg][3]);
            }
        }
    }
    // scatter phase-1 result into T at f1-coords (own rows only)
    #pragma unroll
    for (int sb = 0; sb < 2; sb++)
        #pragma unroll
        for (int gg = 0; gg < 4; gg++)
            #pragma unroll
            for (int j = 0; j < 2; j++) {
                int n = gg * 16 + j * 8 + ncl;
                int u = c01[sb * 64 + n];        // c01[t+1] == u+1 (32-runs)
                float* a4 = acc[sb][gg][j];
                __half2 h0 = __floats2half2_rn(a4[0], a4[1]);
                __half2 h1 = __floats2half2_rn(a4[2], a4[3]);
                int du = (u >> 6) * 16384, cu = (u & 63) >> 3, bu = (u & 7) * 2;
                *(__half2*)(sm01 + du + ml0 * 128 + ((cu ^ (ml0 & 7)) << 4) + bu) = h0;
                *(__half2*)(sm01 + du + (ml0 + 8) * 128 + ((cu ^ ((ml0 + 8) & 7)) << 4) + bu) = h1;
            }
    __syncwarp();

    // ---------------- phase 2: factor 1 ----------------
    #pragma unroll
    for (int sb = 0; sb < 2; sb++) {
        #pragma unroll
        for (int gg = 0; gg < 4; gg++)
            #pragma unroll
            for (int j = 0; j < 2; j++)
                #pragma unroll
                for (int k = 0; k < 4; k++) acc[sb][gg][j][k] = 0.0f;
        const uint32_t a_base = sT + sb * 16384 + arow * 128;
        const uint32_t b_base = sQ + (2 + sb) * 8192 + lrow * 128;  // f=1
        #pragma unroll
        for (int kk = 0; kk < 4; kk++) {
            const uint32_t coff = ((((kk << 1) | lkhi) ^ rowx) << 4);
            uint32_t afr[4];
            LDSM4(afr, a_base + coff);
            uint32_t bfr[4][4];
            #pragma unroll
            for (int gg = 0; gg < 4; gg++)
                LDSM4(bfr[gg], b_base + gg * 2048 + coff);
            #pragma unroll
            for (int gg = 0; gg < 4; gg++) {
                MMA16816(acc[sb][gg][0], afr, bfr[gg][0], bfr[gg][2]);
                MMA16816(acc[sb][gg][1], afr, bfr[gg][1], bfr[gg][3]);
            }
        }
    }
    // scatter to gmem via cs1
    #pragma unroll
    for (int sb = 0; sb < 2; sb++)
        #pragma unroll
        for (int gg = 0; gg < 4; gg++)
            #pragma unroll
            for (int j = 0; j < 2; j++) {
                int n = gg * 16 + j * 8 + ncl;
                int gcol = cs1[sb * 64 + n];     // cs1[t+1] == gcol+1
                float* a4 = acc[sb][gg][j];
                __half2 h0 = __floats2half2_rn(a4[0], a4[1]);
                __half2 h1 = __floats2half2_rn(a4[2], a4[3]);
                *(__half2*)&Wout[(size_t)(row0 + ml0) * IN_F + gcol]     = h0;
                *(__half2*)&Wout[(size_t)(row0 + ml0 + 8) * IN_F + gcol] = h1;
            }
}

// ------- factor 2 + scale + fp16 emit (proven rot_hmma) ---------------------
__global__ __launch_bounds__(256) void rot_hmma(
    const float* __restrict__ WinF, const __half* __restrict__ WinH,
    __half* __restrict__ Wout, int factor, const float* __restrict__ s)
{
    __shared__ __align__(16) char sm[128 * 128 + 64 * 128];
    __shared__ int   cs[64];
    __shared__ float sv[128];
    const uint32_t sa = smem_u32(sm);
    const uint32_t sq = sa + 128 * 128;

    const int d    = blockIdx.x;
    const int rg   = blockIdx.y;
    const int tid  = threadIdx.x;
    const int row0 = rg * 128;

    if (tid < 64) cs[tid] = g_pinv[factor * IN_F + d * 64 + tid];
    if (s != nullptr && tid < 128) sv[tid] = s[row0 + tid];
    __syncthreads();

    #pragma unroll
    for (int i = 0; i < 4; i++) {
        int q = tid + 256 * i;
        int r = q >> 3, c = q & 7;
        char* dst = sm + r * 128 + ((c ^ (r & 7)) << 4);
        int b0 = c * 8;
        if (WinF) {
            *(uint4*)dst = cvt8f(&WinF[(size_t)(row0 + r) * IN_F + cs[b0]]);
        } else {
            *(uint4*)dst = *(const uint4*)&WinH[(size_t)(row0 + r) * IN_F + cs[b0]];
        }
    }
    const float* Qm = g_Q + ((size_t)factor * 64 + d) * 4096;
    #pragma unroll
    for (int i = 0; i < 2; i++) {
        int q = tid + 256 * i;
        int r = q >> 3, c = q & 7;
        uint4 u = cvt8f(&Qm[r * 64 + c * 8]);
        *(uint4*)(sm + 128 * 128 + r * 128 + ((c ^ (r & 7)) << 4)) = u;
    }
    __syncthreads();

    const int wid = tid >> 5, lid = tid & 31;
    const int lrow = (lid & 7) + ((lid >> 3) & 1) * 8;
    const int lkhi = (lid >> 4) & 1;
    const int rowx = lrow & 7;
    const uint32_t a_base = sa + (wid * 16 + lrow) * 128;
    const uint32_t b_base = sq + lrow * 128;

    float acc[4][2][4];
    #pragma unroll
    for (int g = 0; g < 4; g++)
        #pragma unroll
        for (int j = 0; j < 2; j++)
            #pragma unroll
            for (int k = 0; k < 4; k++) acc[g][j][k] = 0.0f;

    #pragma unroll
    for (int kk = 0; kk < 4; kk++) {
        const uint32_t coff = ((((kk << 1) | lkhi) ^ rowx) << 4);
        uint32_t afr[4];
        LDSM4(afr, a_base + coff);
        uint32_t bfr[4][4];
        #pragma unroll
        for (int g = 0; g < 4; g++)
            LDSM4(bfr[g], b_base + g * 2048 + coff);
        #pragma unroll
        for (int g = 0; g < 4; g++) {
            MMA16816(acc[g][0], afr, bfr[g][0], bfr[g][2]);
            MMA16816(acc[g][1], afr, bfr[g][1], bfr[g][3]);
        }
    }

    const int mrow = lid >> 2;
    const int ncl  = (lid & 3) * 2;
    const int mloc0 = wid * 16 + mrow;
    float s0 = 1.0f, s1 = 1.0f;
    if (s != nullptr) { s0 = sv[mloc0]; s1 = sv[mloc0 + 8]; }
    #pragma unroll
    for (int g = 0; g < 4; g++)
        #pragma unroll
        for (int j = 0; j < 2; j++) {
            int n = g * 16 + j * 8 + ncl;
            int gcol = cs[n];
            float* a4 = acc[g][j];
            __half2 h0 = __floats2half2_rn(a4[0] * s0, a4[1] * s0);
            __half2 h1 = __floats2half2_rn(a4[2] * s1, a4[3] * s1);
            *(__half2*)&Wout[(size_t)(row0 + mloc0) * IN_F + gcol]     = h0;
            *(__half2*)&Wout[(size_t)(row0 + mloc0 + 8) * IN_F + gcol] = h1;
        }
}

// ---------------- fp16 mma.sync GEMM: C[16384,4096] = A * B^T + bias -------
#define BKH 64
#define AST 16384
#define STG 32768
#define STAGES 3
#define SMEM_TOTAL (STAGES * STG)       // 98304

__global__ __launch_bounds__(128, 2) void gemm_hmma(
    const __half* __restrict__ A, const __half* __restrict__ B,
    const float* __restrict__ bias, float* __restrict__ C)
{
    extern __shared__ char smem[];
    const uint32_t sb = smem_u32(smem);
    const int tid = threadIdx.x;
    const int wid = tid >> 5, lid = tid & 31;
    const int wm  = wid >> 1, wn = wid & 1;
    const int m0  = blockIdx.y * 128;
    const int n0  = blockIdx.x * 128;

    float acc[4][4][2][4];
    #pragma unroll
    for (int mi = 0; mi < 4; mi++)
        #pragma unroll
        for (int g = 0; g < 4; g++)
            #pragma unroll
            for (int j = 0; j < 2; j++)
                #pragma unroll
                for (int k = 0; k < 4; k++) acc[mi][g][j][k] = 0.0f;

    auto load_stage = [&](int st, int kt) {
        const uint32_t ab = sb + st * STG;
        const uint32_t bb = ab + AST;
        const __half* Ag = A + (size_t)m0 * IN_F + kt * BKH;
        const __half* Bg = B + (size_t)n0 * IN_F + kt * BKH;
        #pragma unroll
        for (int i = 0; i < 8; i++) {
            int q = tid + 128 * i;
            int r = q >> 3, c = q & 7;
            CP_ASYNC16(ab + r * 128 + ((c ^ (r & 7)) << 4), Ag + (size_t)r * IN_F + c * 8);
        }
        #pragma unroll
        for (int i = 0; i < 8; i++) {
            int q = tid + 128 * i;
            int r = q >> 3, c = q & 7;
            CP_ASYNC16(bb + r * 128 + ((c ^ (r & 7)) << 4), Bg + (size_t)r * IN_F + c * 8);
        }
    };

    load_stage(0, 0); CP_COMMIT();
    load_stage(1, 1); CP_COMMIT();

    const int lrow = (lid & 7) + ((lid >> 3) & 1) * 8;
    const int lkhi = (lid >> 4) & 1;
    const int rowx = lrow & 7;

    const int NK = IN_F / BKH;    // 64
    for (int kt = 0; kt < NK; kt++) {
        CP_WAIT1();
        __syncthreads();
        const uint32_t as = sb + (kt % STAGES) * STG;
        const uint32_t bs = as + AST;
        const uint32_t a_base = as + (wm * 64 + lrow) * 128;
        const uint32_t b_base = bs + (wn * 64 + lrow) * 128;

        #pragma unroll
        for (int kk = 0; kk < 4; kk++) {
            const uint32_t coff = ((((kk << 1) | lkhi) ^ rowx) << 4);
            uint32_t afr[4][4];
            #pragma unroll
            for (int mi = 0; mi < 4; mi++)
                LDSM4(afr[mi], a_base + mi * 2048 + coff);
            uint32_t bfr[4][4];
            #pragma unroll
            for (int g = 0; g < 4; g++)
                LDSM4(bfr[g], b_base + g * 2048 + coff);
            #pragma unroll
            for (int mi = 0; mi < 4; mi++)
                #pragma unroll
                for (int g = 0; g < 4; g++) {
                    MMA16816(acc[mi][g][0], afr[mi], bfr[g][0], bfr[g][2]);
                    MMA16816(acc[mi][g][1], afr[mi], bfr[g][1], bfr[g][3]);
                }
        }

        if (kt + 2 < NK) load_stage((kt + 2) % STAGES, kt + 2);
        CP_COMMIT();
    }

    const int mrow = lid >> 2;
    const int ncl  = (lid & 3) * 2;
    #pragma unroll
    for (int g = 0; g < 4; g++)
        #pragma unroll
        for (int j = 0; j < 2; j++) {
            int n = n0 + wn * 64 + g * 16 + j * 8 + ncl;
            float2 bv = *(const float2*)&bias[n];
            #pragma unroll
            for (int mi = 0; mi < 4; mi++) {
                int m = m0 + wm * 64 + mi * 16 + mrow;
                float* a4 = acc[mi][g][j];
                float2 v0 = { a4[0] + bv.x, a4[1] + bv.y };
                float2 v1 = { a4[2] + bv.x, a4[3] + bv.y };
                *(float2*)&C[(size_t)m * OUT_F + n]       = v0;
                *(float2*)&C[(size_t)(m + 8) * OUT_F + n] = v1;
            }
        }
}

// ---------------- launch ----------------
extern "C" void kernel_launch(void* const* d_in, const int* in_sizes, int n_in,
                              void* d_out, int out_size)
{
    const float* x      = (const float*)d_in[0];
    const float* weight = (const float*)d_in[1];
    const float* bias   = (const float*)d_in[2];
    const float* boft_R = (const float*)d_in[3];
    const float* boft_s = (const float*)d_in[4];
    const int*   perm   = (const int*)d_in[5];
    float* out = (float*)d_out;

    __half *hA, *hB, *xh;
    cudaGetSymbolAddress((void**)&hA, g_hA);
    cudaGetSymbolAddress((void**)&hB, g_hB);
    cudaGetSymbolAddress((void**)&xh, g_xh);

    prep_kernel<<<193 + 32768, 256>>>(boft_R, perm, (const float4*)x, (uint4*)xh);

    cudaFuncSetAttribute(rot01_hmma, cudaFuncAttributeMaxDynamicSharedMemorySize, R01_SMEM);
    rot01_hmma<<<dim3(32, 32), 256, R01_SMEM>>>(weight, hB);          // factors 0+1
    rot_hmma<<<dim3(64, 32), 256>>>(nullptr, hB, hA, 2, boft_s);      // factor 2 + s

    cudaFuncSetAttribute(gemm_hmma, cudaFuncAttributeMaxDynamicSharedMemorySize, SMEM_TOTAL);
    gemm_hmma<<<dim3(OUT_F / 128, 16384 / 128), 128, SMEM_TOTAL>>>(xh, hA, bias, out);
}